// round 9
// baseline (speedup 1.0000x reference)
#include <cuda_runtime.h>
#include <cuda_fp16.h>
#include <cstdint>

// ---------------------------------------------------------------------------
// Round 9: fp16-accumulate HMMA (m16n8k16.f16) with per-BK-chunk fp32
// promotion for the 6 big weight GEMMs; fp32-acc retained for attention.
// Everything else identical to Round 8 (13.99 ms).
// ---------------------------------------------------------------------------

#define NTOK 16384
#define CDIM 1024
#define HEADS 16
#define HDIM 64
#define WS 512
#define SHIFTK 256
#define MVD4 4096
#define KCAT 9216
#define HID 4096
#define NZ 512

__device__ float g_lnx  [(long)NTOK * CDIM];
__device__ float g_qkv  [(long)NTOK * 3 * CDIM];
__device__ float g_scores[(long)NZ * WS * WS];
__device__ float g_attn [(long)NTOK * CDIM];
__device__ float g_x1   [(long)NTOK * CDIM];
__device__ float g_x2   [(long)NTOK * CDIM];
__device__ float g_lnb  [(long)NTOK * CDIM];
__device__ float g_h1   [(long)NTOK * HID];

// ---------------------------------------------------------------------------
__global__ __launch_bounds__(256) void ln_kernel(const float* __restrict__ in,
                                                 float* __restrict__ out,
                                                 int shift) {
    int row = blockIdx.x;
    int src = (row + shift) & (NTOK - 1);
    const float* p = in + (long)src * CDIM;
    int t = threadIdx.x;
    float v[4], s = 0.f, s2 = 0.f;
#pragma unroll
    for (int i = 0; i < 4; i++) {
        v[i] = p[t + i * 256];
        s += v[i]; s2 += v[i] * v[i];
    }
#pragma unroll
    for (int o = 16; o; o >>= 1) {
        s  += __shfl_xor_sync(~0u, s, o);
        s2 += __shfl_xor_sync(~0u, s2, o);
    }
    __shared__ float red0[8], red1[8];
    int wid = t >> 5, lid = t & 31;
    if (lid == 0) { red0[wid] = s; red1[wid] = s2; }
    __syncthreads();
    if (t < 32) {
        float a = (t < 8) ? red0[t] : 0.f;
        float b = (t < 8) ? red1[t] : 0.f;
#pragma unroll
        for (int o = 4; o; o >>= 1) {
            a += __shfl_xor_sync(~0u, a, o);
            b += __shfl_xor_sync(~0u, b, o);
        }
        if (t == 0) { red0[0] = a; red1[0] = b; }
    }
    __syncthreads();
    float mean = red0[0] * (1.f / CDIM);
    float var  = red1[0] * (1.f / CDIM) - mean * mean;
    float r = rsqrtf(var + 1e-6f);
    float* q = out + (long)row * CDIM;
#pragma unroll
    for (int i = 0; i < 4; i++) q[t + i * 256] = (v[i] - mean) * r;
}

__global__ __launch_bounds__(256) void softmax_kernel(float* __restrict__ sc) {
    float* p = sc + (long)blockIdx.x * WS;
    int t = threadIdx.x;
    float a = p[t], b = p[t + 256];
    float mx = fmaxf(a, b);
    __shared__ float red[8];
    int wid = t >> 5, lid = t & 31;
#pragma unroll
    for (int o = 16; o; o >>= 1) mx = fmaxf(mx, __shfl_xor_sync(~0u, mx, o));
    if (lid == 0) red[wid] = mx;
    __syncthreads();
    if (t < 32) {
        float v = (t < 8) ? red[t] : -1e30f;
#pragma unroll
        for (int o = 4; o; o >>= 1) v = fmaxf(v, __shfl_xor_sync(~0u, v, o));
        if (t == 0) red[0] = v;
    }
    __syncthreads();
    mx = red[0];
    float ea = __expf(a - mx), eb = __expf(b - mx);
    float sum = ea + eb;
#pragma unroll
    for (int o = 16; o; o >>= 1) sum += __shfl_xor_sync(~0u, sum, o);
    __shared__ float red2[8];
    if (lid == 0) red2[wid] = sum;
    __syncthreads();
    if (t < 32) {
        float v = (t < 8) ? red2[t] : 0.f;
#pragma unroll
        for (int o = 4; o; o >>= 1) v += __shfl_xor_sync(~0u, v, o);
        if (t == 0) red2[0] = v;
    }
    __syncthreads();
    float inv = __frcp_rn(red2[0]);
    p[t] = ea * inv;
    p[t + 256] = eb * inv;
}

__device__ __forceinline__ float gelu_tanh(float v) {
    return 0.5f * v * (1.f + tanhf(0.7978845608028654f * (v + 0.044715f * v * v * v)));
}

__device__ __forceinline__ unsigned h2(float a, float b) {
    __half2 h = __floats2half2_rn(a, b);
    return *(unsigned*)&h;
}

#define MMA_F16(c, a0, a1, a2, a3, b0, b1)                                    \
    asm volatile("mma.sync.aligned.m16n8k16.row.col.f32.f16.f16.f32 "         \
                 "{%0,%1,%2,%3},{%4,%5,%6,%7},{%8,%9},{%0,%1,%2,%3};"         \
                 : "+f"((c)[0]), "+f"((c)[1]), "+f"((c)[2]), "+f"((c)[3])     \
                 : "r"(a0), "r"(a1), "r"(a2), "r"(a3), "r"(b0), "r"(b1))

#define MMA_F16H(d0, d1, a0, a1, a2, a3, b0, b1)                              \
    asm volatile("mma.sync.aligned.m16n8k16.row.col.f16.f16.f16.f16 "         \
                 "{%0,%1},{%2,%3,%4,%5},{%6,%7},{%0,%1};"                     \
                 : "+r"(d0), "+r"(d1)                                         \
                 : "r"(a0), "r"(a1), "r"(a2), "r"(a3), "r"(b0), "r"(b1))

// ---------------------------------------------------------------------------
// fp16 tensor-core GEMM, double-buffered SMEM, 1 barrier/iter, band-swizzled
// CTA order. HACC=1: fp16-accumulate within a BK=32 chunk, promote to fp32.
// ---------------------------------------------------------------------------
#define BM 128
#define BN 128
#define BKH 32
#define SROW 20

template <int HACC>
__global__ __launch_bounds__(256, 2) void gemm_h(
    const float* __restrict__ A0, const float* __restrict__ A1,
    const float* __restrict__ A2, int kb1, int kb2,
    int lda0, int lda1, int lda2,
    const float* __restrict__ B, int ldb, int btrans,
    float* __restrict__ C, int ldc,
    const float* __restrict__ bias, const float* __restrict__ resid,
    int N, int K, float alpha, int epi, int rowShift, int bandw,
    long aZw, long aZh, long bZw, long bZh, long cZw, long cZh)
{
    __shared__ __align__(16) unsigned As[2][BM * SROW];
    __shared__ __align__(16) unsigned Bs[2][BN * SROW];

    const int z = blockIdx.z, w = z >> 4, hh = z & 15;
    const float* Ab = A0 + (long)w * aZw + (long)hh * aZh;
    const float* Bb = B  + (long)w * bZw + (long)hh * bZh;
    float*       Cb = C  + (long)w * cZw + (long)hh * cZh;

    int gx = gridDim.x, gy = gridDim.y;
    int id = blockIdx.y * gx + blockIdx.x;
    int per = bandw * gy;
    int band = id / per, rem = id - band * per;
    int bx = band * bandw + (rem % bandw);
    int by = rem / bandw;

    const int tid = threadIdx.x, lane = tid & 31, wid = tid >> 5;
    const int wm = wid >> 2, wn = wid & 3;
    const int g = lane >> 2, t4 = lane & 3;
    const int m0 = by * BM, n0 = bx * BN;

    float acc[4][4][4];
#pragma unroll
    for (int i = 0; i < 4; i++)
#pragma unroll
        for (int j = 0; j < 4; j++)
#pragma unroll
            for (int r = 0; r < 4; r++) acc[i][j][r] = 0.f;

    const int aM = tid >> 1;
    const int aS = tid & 1;
    const int bn0i = tid & 127;
    const int bS = tid >> 7;

    unsigned sa[8], sb[8];

    auto LOAD = [&](int k0) {
        {
            int gk = k0 + aS * 16;
            const float* p;
            if (gk < kb1)      p = Ab + (long)(m0 + aM) * lda0 + gk;
            else if (gk < kb2) p = A1 + (long)(m0 + aM) * lda1 + (gk - kb1);
            else               p = A2 + (long)(m0 + aM) * lda2 + (gk - kb2);
            float4 f0 = *(const float4*)p;
            float4 f1 = *(const float4*)(p + 4);
            float4 f2 = *(const float4*)(p + 8);
            float4 f3 = *(const float4*)(p + 12);
            sa[0] = h2(f0.x, f0.y); sa[1] = h2(f0.z, f0.w);
            sa[2] = h2(f1.x, f1.y); sa[3] = h2(f1.z, f1.w);
            sa[4] = h2(f2.x, f2.y); sa[5] = h2(f2.z, f2.w);
            sa[6] = h2(f3.x, f3.y); sa[7] = h2(f3.z, f3.w);
        }
        if (btrans) {
            const float* p = Bb + (long)(n0 + aM) * ldb + k0 + aS * 16;
            float4 f0 = *(const float4*)p;
            float4 f1 = *(const float4*)(p + 4);
            float4 f2 = *(const float4*)(p + 8);
            float4 f3 = *(const float4*)(p + 12);
            sb[0] = h2(f0.x, f0.y); sb[1] = h2(f0.z, f0.w);
            sb[2] = h2(f1.x, f1.y); sb[3] = h2(f1.z, f1.w);
            sb[4] = h2(f2.x, f2.y); sb[5] = h2(f2.z, f2.w);
            sb[6] = h2(f3.x, f3.y); sb[7] = h2(f3.z, f3.w);
        } else {
            int gn = n0 + bn0i;
            int ks = k0 + bS * 16;
            float v[16];
#pragma unroll
            for (int r = 0; r < 16; r++)
                v[r] = (gn < N) ? Bb[(long)(ks + r) * ldb + gn] : 0.f;
#pragma unroll
            for (int j = 0; j < 8; j++) sb[j] = h2(v[2 * j], v[2 * j + 1]);
        }
    };

    auto STORE = [&](unsigned* Ad, unsigned* Bd) {
        unsigned* ap = Ad + aM * SROW + aS * 8;
#pragma unroll
        for (int j = 0; j < 4; j++)
            *(uint2*)(ap + 2 * j) = make_uint2(sa[j], sa[j + 4]);
        if (btrans) {
            unsigned* bp = Bd + aM * SROW + aS * 8;
#pragma unroll
            for (int j = 0; j < 4; j++)
                *(uint2*)(bp + 2 * j) = make_uint2(sb[j], sb[j + 4]);
        } else {
            unsigned* bp = Bd + bn0i * SROW + bS * 8;
#pragma unroll
            for (int j = 0; j < 4; j++)
                *(uint2*)(bp + 2 * j) = make_uint2(sb[j], sb[j + 4]);
        }
    };

    auto COMPUTE = [&](const unsigned* Ad, const unsigned* Bd) {
        if constexpr (HACC) {
            // fp16-acc: D starts at 0 each BK chunk, promote to fp32 after.
            uint2 bf[2][4];
#pragma unroll
            for (int s = 0; s < 2; s++)
#pragma unroll
                for (int j = 0; j < 4; j++)
                    bf[s][j] = *(const uint2*)&Bd[(wn * 32 + j * 8 + g) * SROW + s * 8 + 2 * t4];
#pragma unroll
            for (int i = 0; i < 4; i++) {
                int r = wm * 64 + i * 16 + g;
                uint2 lo0 = *(const uint2*)&Ad[r * SROW + 2 * t4];
                uint2 hi0 = *(const uint2*)&Ad[(r + 8) * SROW + 2 * t4];
                uint2 lo1 = *(const uint2*)&Ad[r * SROW + 8 + 2 * t4];
                uint2 hi1 = *(const uint2*)&Ad[(r + 8) * SROW + 8 + 2 * t4];
#pragma unroll
                for (int j = 0; j < 4; j++) {
                    unsigned d0 = 0, d1 = 0;
                    MMA_F16H(d0, d1, lo0.x, hi0.x, lo0.y, hi0.y,
                             bf[0][j].x, bf[0][j].y);
                    MMA_F16H(d0, d1, lo1.x, hi1.x, lo1.y, hi1.y,
                             bf[1][j].x, bf[1][j].y);
                    float2 f0 = __half22float2(*(__half2*)&d0);
                    float2 f1 = __half22float2(*(__half2*)&d1);
                    acc[i][j][0] += f0.x; acc[i][j][1] += f0.y;
                    acc[i][j][2] += f1.x; acc[i][j][3] += f1.y;
                }
            }
        } else {
#pragma unroll
            for (int s = 0; s < 2; s++) {
                uint2 bf[4];
#pragma unroll
                for (int j = 0; j < 4; j++)
                    bf[j] = *(const uint2*)&Bd[(wn * 32 + j * 8 + g) * SROW + s * 8 + 2 * t4];
#pragma unroll
                for (int i = 0; i < 4; i++) {
                    int r = wm * 64 + i * 16 + g;
                    uint2 lo = *(const uint2*)&Ad[r * SROW + s * 8 + 2 * t4];
                    uint2 hi = *(const uint2*)&Ad[(r + 8) * SROW + s * 8 + 2 * t4];
#pragma unroll
                    for (int j = 0; j < 4; j++)
                        MMA_F16(acc[i][j], lo.x, hi.x, lo.y, hi.y, bf[j].x, bf[j].y);
                }
            }
        }
    };

    const int T = K / BKH;
    LOAD(0);
    STORE(As[0], Bs[0]);
    if (T > 1) LOAD(BKH);
    __syncthreads();
    for (int t = 0; t < T; t++) {
        int cur = t & 1;
        if (t + 1 < T) STORE(As[cur ^ 1], Bs[cur ^ 1]);
        if (t + 2 < T) LOAD((t + 2) * BKH);
        COMPUTE(As[cur], Bs[cur]);
        __syncthreads();
    }

    // ---- epilogue ----
#pragma unroll
    for (int i = 0; i < 4; i++) {
        int mr = m0 + wm * 64 + i * 16 + g;
        int r0 = rowShift ? ((mr + rowShift) & (NTOK - 1)) : mr;
        int r1 = rowShift ? ((mr + 8 + rowShift) & (NTOK - 1)) : (mr + 8);
#pragma unroll
        for (int j = 0; j < 4; j++) {
            int col = n0 + wn * 32 + j * 8 + (t4 << 1);
            if (col >= N) continue;
            float b0 = bias ? bias[col]     : 0.f;
            float b1 = bias ? bias[col + 1] : 0.f;
            float v00 = acc[i][j][0] * alpha + b0;
            float v01 = acc[i][j][1] * alpha + b1;
            float v10 = acc[i][j][2] * alpha + b0;
            float v11 = acc[i][j][3] * alpha + b1;
            if (epi == 1) {
                v00 = gelu_tanh(v00); v01 = gelu_tanh(v01);
                v10 = gelu_tanh(v10); v11 = gelu_tanh(v11);
            } else if (epi == 2) {
                const float* q0 = resid + (long)r0 * ldc + col;
                const float* q1 = resid + (long)r1 * ldc + col;
                v00 += q0[0]; v01 += q0[1];
                v10 += q1[0]; v11 += q1[1];
            }
            *(float2*)(Cb + (long)r0 * ldc + col) = make_float2(v00, v01);
            *(float2*)(Cb + (long)r1 * ldc + col) = make_float2(v10, v11);
        }
    }
}

// ---------------------------------------------------------------------------
extern "C" void kernel_launch(void* const* d_in, const int* in_sizes, int n_in,
                              void* d_out, int out_size) {
    const float* x      = (const float*)d_in[0];
    const float* mvn    = (const float*)d_in[1];
    const float* mvc    = (const float*)d_in[2];
    const float* qkv_w  = (const float*)d_in[3];
    const float* qkv_b  = (const float*)d_in[4];
    const float* proj_w = (const float*)d_in[5];
    const float* proj_b = (const float*)d_in[6];
    const float* mv_w1  = (const float*)d_in[7];
    const float* mv_b1  = (const float*)d_in[8];
    const float* mv_w2  = (const float*)d_in[9];
    const float* mv_b2  = (const float*)d_in[10];
    const float* mlp_w1 = (const float*)d_in[11];
    const float* mlp_b1 = (const float*)d_in[12];
    const float* mlp_w2 = (const float*)d_in[13];
    const float* mlp_b2 = (const float*)d_in[14];
    float* out = (float*)d_out;

    float *lnx, *qkv, *scores, *attn, *x1, *x2, *lnb, *h1;
    cudaGetSymbolAddress((void**)&lnx,    g_lnx);
    cudaGetSymbolAddress((void**)&qkv,    g_qkv);
    cudaGetSymbolAddress((void**)&scores, g_scores);
    cudaGetSymbolAddress((void**)&attn,   g_attn);
    cudaGetSymbolAddress((void**)&x1,     g_x1);
    cudaGetSymbolAddress((void**)&x2,     g_x2);
    cudaGetSymbolAddress((void**)&lnb,    g_lnb);
    cudaGetSymbolAddress((void**)&h1,     g_h1);

    // 1) lnx[j] = LN(x[(j+SHIFT)%N])
    ln_kernel<<<NTOK, 256>>>(x, lnx, SHIFTK);

    // 2) qkv = lnx @ qkv_w + qkv_b
    gemm_h<1><<<dim3(3 * CDIM / BN, NTOK / BM, 1), 256>>>(
        lnx, nullptr, nullptr, CDIM, CDIM, CDIM, 0, 0,
        qkv_w, 3 * CDIM, 0, qkv, 3 * CDIM, qkv_b, nullptr,
        3 * CDIM, CDIM, 1.f, 0, 0, 8, 0, 0, 0, 0, 0, 0);

    // 3) scores = Q K^T / 8 per (window, head)
    gemm_h<0><<<dim3(WS / BN, WS / BM, NZ), 256>>>(
        qkv, nullptr, nullptr, CDIM * 4, CDIM * 4, 3 * CDIM, 0, 0,
        qkv + CDIM, 3 * CDIM, 1, scores, WS, nullptr, nullptr,
        WS, HDIM, 0.125f, 0, 0, 4,
        (long)WS * 3 * CDIM, HDIM,
        (long)WS * 3 * CDIM, HDIM,
        (long)WS * WS * HEADS, (long)WS * WS);

    // 4) softmax
    softmax_kernel<<<NZ * WS, 256>>>(scores);

    // 5) attn = P @ V
    gemm_h<0><<<dim3(1, WS / BM, NZ), 256>>>(
        scores, nullptr, nullptr, WS * 2, WS * 2, WS, 0, 0,
        qkv + 2 * CDIM, 3 * CDIM, 0, attn, CDIM, nullptr, nullptr,
        HDIM, WS, 1.f, 0, 0, 1,
        (long)WS * WS * HEADS, (long)WS * WS,
        (long)WS * 3 * CDIM, HDIM,
        (long)WS * CDIM, HDIM);

    // 6) x1[(m+SHIFT)%N] = x[...] + attn@proj_w + proj_b
    gemm_h<1><<<dim3(CDIM / BN, NTOK / BM, 1), 256>>>(
        attn, nullptr, nullptr, CDIM, CDIM, CDIM, 0, 0,
        proj_w, CDIM, 0, x1, CDIM, proj_b, x,
        CDIM, CDIM, 1.f, 2, SHIFTK, 8, 0, 0, 0, 0, 0, 0);

    // 7) mv branch
    ln_kernel<<<NTOK, 256>>>(x1, lnb, 0);
    gemm_h<1><<<dim3(HID / BN, NTOK / BM, 1), 256>>>(
        lnb, mvn, mvc, CDIM, CDIM + MVD4, CDIM, MVD4, MVD4,
        mv_w1, HID, 0, h1, HID, mv_b1, nullptr,
        HID, KCAT, 1.f, 1, 0, 8, 0, 0, 0, 0, 0, 0);
    gemm_h<1><<<dim3(CDIM / BN, NTOK / BM, 1), 256>>>(
        h1, nullptr, nullptr, HID, HID, HID, 0, 0,
        mv_w2, CDIM, 0, x2, CDIM, mv_b2, x1,
        CDIM, HID, 1.f, 2, 0, 8, 0, 0, 0, 0, 0, 0);

    // 8) mlp branch
    ln_kernel<<<NTOK, 256>>>(x2, lnb, 0);
    gemm_h<1><<<dim3(HID / BN, NTOK / BM, 1), 256>>>(
        lnb, nullptr, nullptr, CDIM, CDIM, CDIM, 0, 0,
        mlp_w1, HID, 0, h1, HID, mlp_b1, nullptr,
        HID, CDIM, 1.f, 1, 0, 8, 0, 0, 0, 0, 0, 0);
    gemm_h<1><<<dim3(CDIM / BN, NTOK / BM, 1), 256>>>(
        h1, nullptr, nullptr, HID, HID, HID, 0, 0,
        mlp_w2, CDIM, 0, out, CDIM, mlp_b2, x2,
        CDIM, HID, 1.f, 2, 0, 8, 0, 0, 0, 0, 0, 0);
}

// round 11
// speedup vs baseline: 1.0675x; 1.0675x over previous
#include <cuda_runtime.h>
#include <cuda_fp16.h>
#include <cstdint>

// ---------------------------------------------------------------------------
// Round 10: R8 (fp16 HMMA, fp32 acc) + conflict-free SMEM layout.
// Row stride 16 words, XOR swizzle swz(row)=((row&2)<<2)^(row&4)^((row&8)>>2)
// on word offset (8s+2t4); s-split loader mapping. HACC reverted.
// ---------------------------------------------------------------------------

#define NTOK 16384
#define CDIM 1024
#define HEADS 16
#define HDIM 64
#define WS 512
#define SHIFTK 256
#define MVD4 4096
#define KCAT 9216
#define HID 4096
#define NZ 512

__device__ float g_lnx  [(long)NTOK * CDIM];
__device__ float g_qkv  [(long)NTOK * 3 * CDIM];
__device__ float g_scores[(long)NZ * WS * WS];
__device__ float g_attn [(long)NTOK * CDIM];
__device__ float g_x1   [(long)NTOK * CDIM];
__device__ float g_x2   [(long)NTOK * CDIM];
__device__ float g_lnb  [(long)NTOK * CDIM];
__device__ float g_h1   [(long)NTOK * HID];

// ---------------------------------------------------------------------------
__global__ __launch_bounds__(256) void ln_kernel(const float* __restrict__ in,
                                                 float* __restrict__ out,
                                                 int shift) {
    int row = blockIdx.x;
    int src = (row + shift) & (NTOK - 1);
    const float* p = in + (long)src * CDIM;
    int t = threadIdx.x;
    float v[4], s = 0.f, s2 = 0.f;
#pragma unroll
    for (int i = 0; i < 4; i++) {
        v[i] = p[t + i * 256];
        s += v[i]; s2 += v[i] * v[i];
    }
#pragma unroll
    for (int o = 16; o; o >>= 1) {
        s  += __shfl_xor_sync(~0u, s, o);
        s2 += __shfl_xor_sync(~0u, s2, o);
    }
    __shared__ float red0[8], red1[8];
    int wid = t >> 5, lid = t & 31;
    if (lid == 0) { red0[wid] = s; red1[wid] = s2; }
    __syncthreads();
    if (t < 32) {
        float a = (t < 8) ? red0[t] : 0.f;
        float b = (t < 8) ? red1[t] : 0.f;
#pragma unroll
        for (int o = 4; o; o >>= 1) {
            a += __shfl_xor_sync(~0u, a, o);
            b += __shfl_xor_sync(~0u, b, o);
        }
        if (t == 0) { red0[0] = a; red1[0] = b; }
    }
    __syncthreads();
    float mean = red0[0] * (1.f / CDIM);
    float var  = red1[0] * (1.f / CDIM) - mean * mean;
    float r = rsqrtf(var + 1e-6f);
    float* q = out + (long)row * CDIM;
#pragma unroll
    for (int i = 0; i < 4; i++) q[t + i * 256] = (v[i] - mean) * r;
}

__global__ __launch_bounds__(256) void softmax_kernel(float* __restrict__ sc) {
    float* p = sc + (long)blockIdx.x * WS;
    int t = threadIdx.x;
    float a = p[t], b = p[t + 256];
    float mx = fmaxf(a, b);
    __shared__ float red[8];
    int wid = t >> 5, lid = t & 31;
#pragma unroll
    for (int o = 16; o; o >>= 1) mx = fmaxf(mx, __shfl_xor_sync(~0u, mx, o));
    if (lid == 0) red[wid] = mx;
    __syncthreads();
    if (t < 32) {
        float v = (t < 8) ? red[t] : -1e30f;
#pragma unroll
        for (int o = 4; o; o >>= 1) v = fmaxf(v, __shfl_xor_sync(~0u, v, o));
        if (t == 0) red[0] = v;
    }
    __syncthreads();
    mx = red[0];
    float ea = __expf(a - mx), eb = __expf(b - mx);
    float sum = ea + eb;
#pragma unroll
    for (int o = 16; o; o >>= 1) sum += __shfl_xor_sync(~0u, sum, o);
    __shared__ float red2[8];
    if (lid == 0) red2[wid] = sum;
    __syncthreads();
    if (t < 32) {
        float v = (t < 8) ? red2[t] : 0.f;
#pragma unroll
        for (int o = 4; o; o >>= 1) v += __shfl_xor_sync(~0u, v, o);
        if (t == 0) red2[0] = v;
    }
    __syncthreads();
    float inv = __frcp_rn(red2[0]);
    p[t] = ea * inv;
    p[t + 256] = eb * inv;
}

__device__ __forceinline__ float gelu_tanh(float v) {
    return 0.5f * v * (1.f + tanhf(0.7978845608028654f * (v + 0.044715f * v * v * v)));
}

__device__ __forceinline__ unsigned h2(float a, float b) {
    __half2 h = __floats2half2_rn(a, b);
    return *(unsigned*)&h;
}

#define MMA_F16(c, a0, a1, a2, a3, b0, b1)                                    \
    asm volatile("mma.sync.aligned.m16n8k16.row.col.f32.f16.f16.f32 "         \
                 "{%0,%1,%2,%3},{%4,%5,%6,%7},{%8,%9},{%0,%1,%2,%3};"         \
                 : "+f"((c)[0]), "+f"((c)[1]), "+f"((c)[2]), "+f"((c)[3])     \
                 : "r"(a0), "r"(a1), "r"(a2), "r"(a3), "r"(b0), "r"(b1))

// swizzle: word offset within 16-word row; row bits 1..3 spread banks.
__device__ __forceinline__ int swz16(int row) {
    return ((row & 2) << 2) ^ (row & 4) ^ ((row & 8) >> 2);
}

// ---------------------------------------------------------------------------
// fp16 tensor-core GEMM, double-buffered SMEM, 1 barrier/iter, band-swizzled
// CTA order, conflict-free swizzled SMEM (row stride 16 words).
// ---------------------------------------------------------------------------
#define BM 128
#define BN 128
#define BKH 32
#define SROW 16

__global__ __launch_bounds__(256, 2) void gemm_h(
    const float* __restrict__ A0, const float* __restrict__ A1,
    const float* __restrict__ A2, int kb1, int kb2,
    int lda0, int lda1, int lda2,
    const float* __restrict__ B, int ldb, int btrans,
    float* __restrict__ C, int ldc,
    const float* __restrict__ bias, const float* __restrict__ resid,
    int N, int K, float alpha, int epi, int rowShift, int bandw,
    long aZw, long aZh, long bZw, long bZh, long cZw, long cZh)
{
    __shared__ __align__(16) unsigned As[2][BM * SROW];
    __shared__ __align__(16) unsigned Bs[2][BN * SROW];

    const int z = blockIdx.z, w = z >> 4, hh = z & 15;
    const float* Ab = A0 + (long)w * aZw + (long)hh * aZh;
    const float* Bb = B  + (long)w * bZw + (long)hh * bZh;
    float*       Cb = C  + (long)w * cZw + (long)hh * cZh;

    int gx = gridDim.x, gy = gridDim.y;
    int id = blockIdx.y * gx + blockIdx.x;
    int per = bandw * gy;
    int band = id / per, rem = id - band * per;
    int bx = band * bandw + (rem % bandw);
    int by = rem / bandw;

    const int tid = threadIdx.x, lane = tid & 31, wid = tid >> 5;
    const int wm = wid >> 2, wn = wid & 3;
    const int g = lane >> 2, t4 = lane & 3;
    const int m0 = by * BM, n0 = bx * BN;

    float acc[4][4][4];
#pragma unroll
    for (int i = 0; i < 4; i++)
#pragma unroll
        for (int j = 0; j < 4; j++)
#pragma unroll
            for (int r = 0; r < 4; r++) acc[i][j][r] = 0.f;

    // s-split loader mapping: rows 0..127, k16-step = tid>>7
    const int aM = tid & 127;
    const int aS = tid >> 7;
    const int aSw = swz16(aM);

    unsigned sa[8], sb[8];

    auto LOAD = [&](int k0) {
        {
            int gk = k0 + aS * 16;
            const float* p;
            if (gk < kb1)      p = Ab + (long)(m0 + aM) * lda0 + gk;
            else if (gk < kb2) p = A1 + (long)(m0 + aM) * lda1 + (gk - kb1);
            else               p = A2 + (long)(m0 + aM) * lda2 + (gk - kb2);
            float4 f0 = *(const float4*)p;
            float4 f1 = *(const float4*)(p + 4);
            float4 f2 = *(const float4*)(p + 8);
            float4 f3 = *(const float4*)(p + 12);
            sa[0] = h2(f0.x, f0.y); sa[1] = h2(f0.z, f0.w);
            sa[2] = h2(f1.x, f1.y); sa[3] = h2(f1.z, f1.w);
            sa[4] = h2(f2.x, f2.y); sa[5] = h2(f2.z, f2.w);
            sa[6] = h2(f3.x, f3.y); sa[7] = h2(f3.z, f3.w);
        }
        if (btrans) {
            const float* p = Bb + (long)(n0 + aM) * ldb + k0 + aS * 16;
            float4 f0 = *(const float4*)p;
            float4 f1 = *(const float4*)(p + 4);
            float4 f2 = *(const float4*)(p + 8);
            float4 f3 = *(const float4*)(p + 12);
            sb[0] = h2(f0.x, f0.y); sb[1] = h2(f0.z, f0.w);
            sb[2] = h2(f1.x, f1.y); sb[3] = h2(f1.z, f1.w);
            sb[4] = h2(f2.x, f2.y); sb[5] = h2(f2.z, f2.w);
            sb[6] = h2(f3.x, f3.y); sb[7] = h2(f3.z, f3.w);
        } else {
            int gn = n0 + aM;
            int ks = k0 + aS * 16;
            float v[16];
#pragma unroll
            for (int r = 0; r < 16; r++)
                v[r] = (gn < N) ? Bb[(long)(ks + r) * ldb + gn] : 0.f;
#pragma unroll
            for (int j = 0; j < 8; j++) sb[j] = h2(v[2 * j], v[2 * j + 1]);
        }
    };

    auto STORE = [&](unsigned* Ad, unsigned* Bd) {
        unsigned* ap = Ad + aM * SROW;
#pragma unroll
        for (int j = 0; j < 4; j++)
            *(uint2*)(ap + ((aS * 8 + 2 * j) ^ aSw)) = make_uint2(sa[j], sa[j + 4]);
        unsigned* bp = Bd + aM * SROW;
#pragma unroll
        for (int j = 0; j < 4; j++)
            *(uint2*)(bp + ((aS * 8 + 2 * j) ^ aSw)) = make_uint2(sb[j], sb[j + 4]);
    };

    const int sg = ((g & 2) << 2) ^ (g & 4);   // swz of rows with bits0-2 = g
    auto COMPUTE = [&](const unsigned* Ad, const unsigned* Bd) {
#pragma unroll
        for (int s = 0; s < 2; s++) {
            const int off = (s * 8 + 2 * t4) ^ sg;
            uint2 bf[4];
#pragma unroll
            for (int j = 0; j < 4; j++)
                bf[j] = *(const uint2*)&Bd[(wn * 32 + j * 8 + g) * SROW +
                                           (off ^ ((j & 1) << 1))];
#pragma unroll
            for (int i = 0; i < 4; i++) {
                int r = wm * 64 + i * 16 + g;
                uint2 lo = *(const uint2*)&Ad[r * SROW + off];
                uint2 hi = *(const uint2*)&Ad[(r + 8) * SROW + (off ^ 2)];
#pragma unroll
                for (int j = 0; j < 4; j++)
                    MMA_F16(acc[i][j], lo.x, hi.x, lo.y, hi.y, bf[j].x, bf[j].y);
            }
        }
    };

    const int T = K / BKH;
    LOAD(0);
    STORE(As[0], Bs[0]);
    if (T > 1) LOAD(BKH);
    __syncthreads();
    for (int t = 0; t < T; t++) {
        int cur = t & 1;
        if (t + 1 < T) STORE(As[cur ^ 1], Bs[cur ^ 1]);   // regs hold tile t+1
        if (t + 2 < T) LOAD((t + 2) * BKH);
        COMPUTE(As[cur], Bs[cur]);
        __syncthreads();
    }

    // ---- epilogue ----
#pragma unroll
    for (int i = 0; i < 4; i++) {
        int mr = m0 + wm * 64 + i * 16 + g;
        int r0 = rowShift ? ((mr + rowShift) & (NTOK - 1)) : mr;
        int r1 = rowShift ? ((mr + 8 + rowShift) & (NTOK - 1)) : (mr + 8);
#pragma unroll
        for (int j = 0; j < 4; j++) {
            int col = n0 + wn * 32 + j * 8 + (t4 << 1);
            if (col >= N) continue;
            float b0 = bias ? bias[col]     : 0.f;
            float b1 = bias ? bias[col + 1] : 0.f;
            float v00 = acc[i][j][0] * alpha + b0;
            float v01 = acc[i][j][1] * alpha + b1;
            float v10 = acc[i][j][2] * alpha + b0;
            float v11 = acc[i][j][3] * alpha + b1;
            if (epi == 1) {
                v00 = gelu_tanh(v00); v01 = gelu_tanh(v01);
                v10 = gelu_tanh(v10); v11 = gelu_tanh(v11);
            } else if (epi == 2) {
                const float* q0 = resid + (long)r0 * ldc + col;
                const float* q1 = resid + (long)r1 * ldc + col;
                v00 += q0[0]; v01 += q0[1];
                v10 += q1[0]; v11 += q1[1];
            }
            *(float2*)(Cb + (long)r0 * ldc + col) = make_float2(v00, v01);
            *(float2*)(Cb + (long)r1 * ldc + col) = make_float2(v10, v11);
        }
    }
}

// ---------------------------------------------------------------------------
extern "C" void kernel_launch(void* const* d_in, const int* in_sizes, int n_in,
                              void* d_out, int out_size) {
    const float* x      = (const float*)d_in[0];
    const float* mvn    = (const float*)d_in[1];
    const float* mvc    = (const float*)d_in[2];
    const float* qkv_w  = (const float*)d_in[3];
    const float* qkv_b  = (const float*)d_in[4];
    const float* proj_w = (const float*)d_in[5];
    const float* proj_b = (const float*)d_in[6];
    const float* mv_w1  = (const float*)d_in[7];
    const float* mv_b1  = (const float*)d_in[8];
    const float* mv_w2  = (const float*)d_in[9];
    const float* mv_b2  = (const float*)d_in[10];
    const float* mlp_w1 = (const float*)d_in[11];
    const float* mlp_b1 = (const float*)d_in[12];
    const float* mlp_w2 = (const float*)d_in[13];
    const float* mlp_b2 = (const float*)d_in[14];
    float* out = (float*)d_out;

    float *lnx, *qkv, *scores, *attn, *x1, *x2, *lnb, *h1;
    cudaGetSymbolAddress((void**)&lnx,    g_lnx);
    cudaGetSymbolAddress((void**)&qkv,    g_qkv);
    cudaGetSymbolAddress((void**)&scores, g_scores);
    cudaGetSymbolAddress((void**)&attn,   g_attn);
    cudaGetSymbolAddress((void**)&x1,     g_x1);
    cudaGetSymbolAddress((void**)&x2,     g_x2);
    cudaGetSymbolAddress((void**)&lnb,    g_lnb);
    cudaGetSymbolAddress((void**)&h1,     g_h1);

    // 1) lnx[j] = LN(x[(j+SHIFT)%N])
    ln_kernel<<<NTOK, 256>>>(x, lnx, SHIFTK);

    // 2) qkv = lnx @ qkv_w + qkv_b
    gemm_h<<<dim3(3 * CDIM / BN, NTOK / BM, 1), 256>>>(
        lnx, nullptr, nullptr, CDIM, CDIM, CDIM, 0, 0,
        qkv_w, 3 * CDIM, 0, qkv, 3 * CDIM, qkv_b, nullptr,
        3 * CDIM, CDIM, 1.f, 0, 0, 8, 0, 0, 0, 0, 0, 0);

    // 3) scores = Q K^T / 8 per (window, head)
    gemm_h<<<dim3(WS / BN, WS / BM, NZ), 256>>>(
        qkv, nullptr, nullptr, CDIM * 4, CDIM * 4, 3 * CDIM, 0, 0,
        qkv + CDIM, 3 * CDIM, 1, scores, WS, nullptr, nullptr,
        WS, HDIM, 0.125f, 0, 0, 4,
        (long)WS * 3 * CDIM, HDIM,
        (long)WS * 3 * CDIM, HDIM,
        (long)WS * WS * HEADS, (long)WS * WS);

    // 4) softmax
    softmax_kernel<<<NZ * WS, 256>>>(scores);

    // 5) attn = P @ V
    gemm_h<<<dim3(1, WS / BM, NZ), 256>>>(
        scores, nullptr, nullptr, WS * 2, WS * 2, WS, 0, 0,
        qkv + 2 * CDIM, 3 * CDIM, 0, attn, CDIM, nullptr, nullptr,
        HDIM, WS, 1.f, 0, 0, 1,
        (long)WS * WS * HEADS, (long)WS * WS,
        (long)WS * 3 * CDIM, HDIM,
        (long)WS * CDIM, HDIM);

    // 6) x1[(m+SHIFT)%N] = x[...] + attn@proj_w + proj_b
    gemm_h<<<dim3(CDIM / BN, NTOK / BM, 1), 256>>>(
        attn, nullptr, nullptr, CDIM, CDIM, CDIM, 0, 0,
        proj_w, CDIM, 0, x1, CDIM, proj_b, x,
        CDIM, CDIM, 1.f, 2, SHIFTK, 8, 0, 0, 0, 0, 0, 0);

    // 7) mv branch
    ln_kernel<<<NTOK, 256>>>(x1, lnb, 0);
    gemm_h<<<dim3(HID / BN, NTOK / BM, 1), 256>>>(
        lnb, mvn, mvc, CDIM, CDIM + MVD4, CDIM, MVD4, MVD4,
        mv_w1, HID, 0, h1, HID, mv_b1, nullptr,
        HID, KCAT, 1.f, 1, 0, 8, 0, 0, 0, 0, 0, 0);
    gemm_h<<<dim3(CDIM / BN, NTOK / BM, 1), 256>>>(
        h1, nullptr, nullptr, HID, HID, HID, 0, 0,
        mv_w2, CDIM, 0, x2, CDIM, mv_b2, x1,
        CDIM, HID, 1.f, 2, 0, 8, 0, 0, 0, 0, 0, 0);

    // 8) mlp branch
    ln_kernel<<<NTOK, 256>>>(x2, lnb, 0);
    gemm_h<<<dim3(HID / BN, NTOK / BM, 1), 256>>>(
        lnb, nullptr, nullptr, CDIM, CDIM, CDIM, 0, 0,
        mlp_w1, HID, 0, h1, HID, mlp_b1, nullptr,
        HID, CDIM, 1.f, 1, 0, 8, 0, 0, 0, 0, 0, 0);
    gemm_h<<<dim3(CDIM / BN, NTOK / BM, 1), 256>>>(
        h1, nullptr, nullptr, HID, HID, HID, 0, 0,
        mlp_w2, CDIM, 0, out, CDIM, mlp_b2, x2,
        CDIM, HID, 1.f, 2, 0, 8, 0, 0, 0, 0, 0, 0);
}

// round 13
// speedup vs baseline: 2.1040x; 1.9709x over previous
#include <cuda_runtime.h>
#include <cuda_fp16.h>
#include <cstdint>

// ---------------------------------------------------------------------------
// Round 13 (= fixed Round 12): cp.async + ldmatrix fp16 GEMM (gemm_a) for the
// 6 big GEMMs; inputs pre-converted to fp16 (weights transposed to [N,K]);
// LN/GELU/PV producers write fp16. Attention on R8's proven gemm_h (verbatim
// loader). No static guards.
// ---------------------------------------------------------------------------

#define NTOK 16384
#define CDIM 1024
#define HEADS 16
#define HDIM 64
#define WS 512
#define SHIFTK 256
#define MVD4 4096
#define KCAT 9216
#define HID 4096
#define NZ 512

// fp32 buffers
__device__ float g_qkv   [(long)NTOK * 3 * CDIM];
__device__ float g_scores[(long)NZ * WS * WS];
__device__ float g_x1    [(long)NTOK * CDIM];
__device__ float g_x2    [(long)NTOK * CDIM];
// fp16 buffers
__device__ __half g_qkvwT[(long)3 * CDIM * CDIM];
__device__ __half g_projwT[(long)CDIM * CDIM];
__device__ __half g_mv1T [(long)HID * KCAT];
__device__ __half g_mv2T [(long)CDIM * HID];
__device__ __half g_mlp1T[(long)HID * CDIM];
__device__ __half g_mlp2T[(long)CDIM * HID];
__device__ __half g_mvnh [(long)NTOK * MVD4];
__device__ __half g_mvch [(long)NTOK * MVD4];
__device__ __half g_lnxh [(long)NTOK * CDIM];
__device__ __half g_lnbh [(long)NTOK * CDIM];
__device__ __half g_h1h  [(long)NTOK * HID];
__device__ __half g_attnh[(long)NTOK * CDIM];

// ======================= helpers =======================
__device__ __forceinline__ uint32_t smem_u32(const void* p) {
    uint32_t a;
    asm("{ .reg .u64 t; cvta.to.shared.u64 t, %1; cvt.u32.u64 %0, t; }"
        : "=r"(a) : "l"(p));
    return a;
}
__device__ __forceinline__ float gelu_tanh(float v) {
    return 0.5f * v * (1.f + tanhf(0.7978845608028654f * (v + 0.044715f * v * v * v)));
}
__device__ __forceinline__ unsigned h2(float a, float b) {
    __half2 h = __floats2half2_rn(a, b);
    return *(unsigned*)&h;
}
#define MMA_F16(c, a0, a1, a2, a3, b0, b1)                                    \
    asm volatile("mma.sync.aligned.m16n8k16.row.col.f32.f16.f16.f32 "         \
                 "{%0,%1,%2,%3},{%4,%5,%6,%7},{%8,%9},{%0,%1,%2,%3};"         \
                 : "+f"((c)[0]), "+f"((c)[1]), "+f"((c)[2]), "+f"((c)[3])     \
                 : "r"(a0), "r"(a1), "r"(a2), "r"(a3), "r"(b0), "r"(b1))
#define LDSM4(r0, r1, r2, r3, a)                                              \
    asm volatile("ldmatrix.sync.aligned.m8n8.x4.shared.b16 {%0,%1,%2,%3}, [%4];" \
                 : "=r"(r0), "=r"(r1), "=r"(r2), "=r"(r3) : "r"(a))
#define CPA(dst, src)                                                         \
    asm volatile("cp.async.cg.shared.global [%0], [%1], 16;"                  \
                 :: "r"(dst), "l"(src))

// ======================= conversion kernels =======================
// transpose + cvt: W[K,N] f32 -> WT[N,K] f16
__global__ __launch_bounds__(256) void wt_kernel(const float* __restrict__ W,
                                                 __half* __restrict__ WT,
                                                 int K, int N) {
    __shared__ float tile[32][33];
    int n0 = blockIdx.x * 32, k0 = blockIdx.y * 32;
    int tx = threadIdx.x & 31, ty = threadIdx.x >> 5;   // 32 x 8
#pragma unroll
    for (int r = 0; r < 4; r++)
        tile[ty + 8 * r][tx] = W[(long)(k0 + ty + 8 * r) * N + n0 + tx];
    __syncthreads();
#pragma unroll
    for (int r = 0; r < 4; r++)
        WT[(long)(n0 + ty + 8 * r) * K + k0 + tx] =
            __float2half_rn(tile[tx][ty + 8 * r]);
}

// flat f32 -> f16
__global__ __launch_bounds__(256) void cvt_kernel(const float4* __restrict__ s,
                                                  __half2* __restrict__ d,
                                                  long n4) {
    long i = (long)blockIdx.x * blockDim.x + threadIdx.x;
    long stride = (long)gridDim.x * blockDim.x;
    for (; i < n4; i += stride) {
        float4 v = s[i];
        d[2 * i]     = __floats2half2_rn(v.x, v.y);
        d[2 * i + 1] = __floats2half2_rn(v.z, v.w);
    }
}

// ======================= LN (fp16 out) / softmax =======================
__global__ __launch_bounds__(256) void ln_kernel(const float* __restrict__ in,
                                                 __half* __restrict__ out,
                                                 int shift) {
    int row = blockIdx.x;
    int src = (row + shift) & (NTOK - 1);
    const float* p = in + (long)src * CDIM;
    int t = threadIdx.x;
    float v[4], s = 0.f, s2 = 0.f;
#pragma unroll
    for (int i = 0; i < 4; i++) {
        v[i] = p[t + i * 256];
        s += v[i]; s2 += v[i] * v[i];
    }
#pragma unroll
    for (int o = 16; o; o >>= 1) {
        s  += __shfl_xor_sync(~0u, s, o);
        s2 += __shfl_xor_sync(~0u, s2, o);
    }
    __shared__ float red0[8], red1[8];
    int wid = t >> 5, lid = t & 31;
    if (lid == 0) { red0[wid] = s; red1[wid] = s2; }
    __syncthreads();
    if (t < 32) {
        float a = (t < 8) ? red0[t] : 0.f;
        float b = (t < 8) ? red1[t] : 0.f;
#pragma unroll
        for (int o = 4; o; o >>= 1) {
            a += __shfl_xor_sync(~0u, a, o);
            b += __shfl_xor_sync(~0u, b, o);
        }
        if (t == 0) { red0[0] = a; red1[0] = b; }
    }
    __syncthreads();
    float mean = red0[0] * (1.f / CDIM);
    float var  = red1[0] * (1.f / CDIM) - mean * mean;
    float r = rsqrtf(var + 1e-6f);
    __half* q = out + (long)row * CDIM;
#pragma unroll
    for (int i = 0; i < 4; i++)
        q[t + i * 256] = __float2half_rn((v[i] - mean) * r);
}

__global__ __launch_bounds__(256) void softmax_kernel(float* __restrict__ sc) {
    float* p = sc + (long)blockIdx.x * WS;
    int t = threadIdx.x;
    float a = p[t], b = p[t + 256];
    float mx = fmaxf(a, b);
    __shared__ float red[8];
    int wid = t >> 5, lid = t & 31;
#pragma unroll
    for (int o = 16; o; o >>= 1) mx = fmaxf(mx, __shfl_xor_sync(~0u, mx, o));
    if (lid == 0) red[wid] = mx;
    __syncthreads();
    if (t < 32) {
        float v = (t < 8) ? red[t] : -1e30f;
#pragma unroll
        for (int o = 4; o; o >>= 1) v = fmaxf(v, __shfl_xor_sync(~0u, v, o));
        if (t == 0) red[0] = v;
    }
    __syncthreads();
    mx = red[0];
    float ea = __expf(a - mx), eb = __expf(b - mx);
    float sum = ea + eb;
#pragma unroll
    for (int o = 16; o; o >>= 1) sum += __shfl_xor_sync(~0u, sum, o);
    __shared__ float red2[8];
    if (lid == 0) red2[wid] = sum;
    __syncthreads();
    if (t < 32) {
        float v = (t < 8) ? red2[t] : 0.f;
#pragma unroll
        for (int o = 4; o; o >>= 1) v += __shfl_xor_sync(~0u, v, o);
        if (t == 0) red2[0] = v;
    }
    __syncthreads();
    float inv = __frcp_rn(red2[0]);
    p[t] = ea * inv;
    p[t + 256] = eb * inv;
}

// ======================= gemm_a: cp.async + ldmatrix fp16 GEMM ==========
// BM=BN=128, BK=32 halves, 3-stage cp.async pipeline, 256 threads (2x4
// warps, warp tile 64x32). SMEM row stride 40 halves (80B): 20r mod 32
// cycles all banks -> ldmatrix conflict-free.
#define SROWH 40
#define ABYTES (128 * SROWH * 2)
#define STAGEB (2 * ABYTES)
#define SMEMA (3 * STAGEB)

__global__ __launch_bounds__(256, 2) void gemm_a(
    const __half* __restrict__ A0, const __half* __restrict__ A1,
    const __half* __restrict__ A2, int kb1, int kb2,
    int lda0, int lda1, int lda2,
    const __half* __restrict__ Bt, int ldb,
    float* __restrict__ C, __half* __restrict__ Ch, int ldc,
    const float* __restrict__ bias, const float* __restrict__ resid,
    int K, int epi, int rowShift, int bandw)
{
    extern __shared__ __half dsm[];
    const uint32_t sb0 = smem_u32(dsm);

    int gx = gridDim.x, gy = gridDim.y;
    int id = blockIdx.y * gx + blockIdx.x;
    int per = bandw * gy;
    int band = id / per, rem = id - band * per;
    int bx = band * bandw + (rem % bandw);
    int by = rem / bandw;
    const int m0 = by * 128, n0 = bx * 128;

    const int tid = threadIdx.x, lane = tid & 31, wid = tid >> 5;
    const int wm = wid >> 2, wn = wid & 3;
    const int g = lane >> 2, t4 = lane & 3;

    float acc[4][4][4];
#pragma unroll
    for (int i = 0; i < 4; i++)
#pragma unroll
        for (int j = 0; j < 4; j++)
#pragma unroll
            for (int r = 0; r < 4; r++) acc[i][j][r] = 0.f;

    const int cRow = tid >> 1;
    const int cSeg = tid & 1;
    const uint32_t cOff = (uint32_t)(cRow * SROWH + cSeg * 16) * 2;
    const __half* bSrc = Bt + (long)(n0 + cRow) * ldb + cSeg * 16;

    auto ISSUE = [&](int stage, int k0) {
        uint32_t base = sb0 + stage * STAGEB;
        int gk = k0 + cSeg * 16;
        const __half* ap;
        if (gk < kb1)      ap = A0 + (long)(m0 + cRow) * lda0 + gk;
        else if (gk < kb2) ap = A1 + (long)(m0 + cRow) * lda1 + (gk - kb1);
        else               ap = A2 + (long)(m0 + cRow) * lda2 + (gk - kb2);
        uint32_t ad = base + cOff;
        CPA(ad, ap); CPA(ad + 16, ap + 8);
        uint32_t bd = base + ABYTES + cOff;
        const __half* bp = bSrc + k0;
        CPA(bd, bp); CPA(bd + 16, bp + 8);
        asm volatile("cp.async.commit_group;");
    };

    const int aRowB = (wm * 64 + (lane & 15)) * (SROWH * 2) + (lane >> 4) * 16;
    const int bRowB = (wn * 32 + ((lane >> 4) & 1) * 8 + (lane & 7)) * (SROWH * 2)
                      + ((lane >> 3) & 1) * 16;

    auto COMPUTE = [&](int stage) {
        uint32_t aB = sb0 + stage * STAGEB + aRowB;
        uint32_t bB = sb0 + stage * STAGEB + ABYTES + bRowB;
#pragma unroll
        for (int s = 0; s < 2; s++) {
            uint32_t bw[8];
            LDSM4(bw[0], bw[1], bw[2], bw[3], bB + s * 32);
            LDSM4(bw[4], bw[5], bw[6], bw[7], bB + 16 * (SROWH * 2) + s * 32);
#pragma unroll
            for (int i = 0; i < 4; i++) {
                uint32_t aw[4];
                LDSM4(aw[0], aw[1], aw[2], aw[3],
                      aB + i * 16 * (SROWH * 2) + s * 32);
#pragma unroll
                for (int j = 0; j < 4; j++)
                    MMA_F16(acc[i][j], aw[0], aw[1], aw[2], aw[3],
                            bw[2 * j], bw[2 * j + 1]);
            }
        }
    };

    const int T = K / 32;
    ISSUE(0, 0);
    ISSUE(1, 32);
    for (int t = 0; t < T; t++) {
        if (t + 2 <= T) asm volatile("cp.async.wait_group 1;" ::: "memory");
        else            asm volatile("cp.async.wait_group 0;" ::: "memory");
        __syncthreads();
        if (t + 2 < T) ISSUE((t + 2) % 3, (t + 2) * 32);
        COMPUTE(t % 3);
    }

    // ---- epilogue ----
#pragma unroll
    for (int i = 0; i < 4; i++) {
        int mr = m0 + wm * 64 + i * 16 + g;
        int r0 = rowShift ? ((mr + rowShift) & (NTOK - 1)) : mr;
        int r1 = rowShift ? ((mr + 8 + rowShift) & (NTOK - 1)) : (mr + 8);
#pragma unroll
        for (int j = 0; j < 4; j++) {
            int col = n0 + wn * 32 + j * 8 + (t4 << 1);
            float b0 = bias[col], b1 = bias[col + 1];
            float v00 = acc[i][j][0] + b0;
            float v01 = acc[i][j][1] + b1;
            float v10 = acc[i][j][2] + b0;
            float v11 = acc[i][j][3] + b1;
            if (epi == 1) {
                *(__half2*)(Ch + (long)r0 * ldc + col) =
                    __floats2half2_rn(gelu_tanh(v00), gelu_tanh(v01));
                *(__half2*)(Ch + (long)r1 * ldc + col) =
                    __floats2half2_rn(gelu_tanh(v10), gelu_tanh(v11));
            } else {
                if (epi == 2) {
                    const float* q0 = resid + (long)r0 * ldc + col;
                    const float* q1 = resid + (long)r1 * ldc + col;
                    v00 += q0[0]; v01 += q0[1];
                    v10 += q1[0]; v11 += q1[1];
                }
                *(float2*)(C + (long)r0 * ldc + col) = make_float2(v00, v01);
                *(float2*)(C + (long)r1 * ldc + col) = make_float2(v10, v11);
            }
        }
    }
}

// ======================= gemm_h (attention only, R8-exact) ==============
#define BM 128
#define BN 128
#define BKH 32
#define SROW 20

__global__ __launch_bounds__(256, 2) void gemm_h(
    const float* __restrict__ A0, int lda0,
    const float* __restrict__ B, int ldb, int btrans,
    float* __restrict__ C, int ldc,
    int N, int K, float alpha, int hout, int bandw,
    long aZw, long aZh, long bZw, long bZh, long cZw, long cZh)
{
    __shared__ __align__(16) unsigned As[2][BM * SROW];
    __shared__ __align__(16) unsigned Bs[2][BN * SROW];

    const int z = blockIdx.z, w = z >> 4, hh = z & 15;
    const float* Ab = A0 + (long)w * aZw + (long)hh * aZh;
    const float* Bb = B  + (long)w * bZw + (long)hh * bZh;
    float*       Cb  = C + (long)w * cZw + (long)hh * cZh;
    __half*      Cbh = ((__half*)C) + (long)w * cZw + (long)hh * cZh;

    int gx = gridDim.x, gy = gridDim.y;
    int id = blockIdx.y * gx + blockIdx.x;
    int per = bandw * gy;
    int band = id / per, rem = id - band * per;
    int bx = band * bandw + (rem % bandw);
    int by = rem / bandw;

    const int tid = threadIdx.x, lane = tid & 31, wid = tid >> 5;
    const int wm = wid >> 2, wn = wid & 3;
    const int g = lane >> 2, t4 = lane & 3;
    const int m0 = by * BM, n0 = bx * BN;

    float acc[4][4][4];
#pragma unroll
    for (int i = 0; i < 4; i++)
#pragma unroll
        for (int j = 0; j < 4; j++)
#pragma unroll
            for (int r = 0; r < 4; r++) acc[i][j][r] = 0.f;

    // R8-exact loader: thread owns one full k16 step (16 halves).
    const int aM = tid >> 1;            // 0..127 row
    const int aS = tid & 1;             // k16 step owned
    const int bn0i = tid & 127;         // B-normal: col
    const int bS = tid >> 7;            // B-normal: step owned

    unsigned sa[8], sb[8];

    auto LOAD = [&](int k0) {
        {
            const float* p = Ab + (long)(m0 + aM) * lda0 + k0 + aS * 16;
            float4 f0 = *(const float4*)p;
            float4 f1 = *(const float4*)(p + 4);
            float4 f2 = *(const float4*)(p + 8);
            float4 f3 = *(const float4*)(p + 12);
            sa[0] = h2(f0.x, f0.y); sa[1] = h2(f0.z, f0.w);
            sa[2] = h2(f1.x, f1.y); sa[3] = h2(f1.z, f1.w);
            sa[4] = h2(f2.x, f2.y); sa[5] = h2(f2.z, f2.w);
            sa[6] = h2(f3.x, f3.y); sa[7] = h2(f3.z, f3.w);
        }
        if (btrans) {
            const float* p = Bb + (long)(n0 + aM) * ldb + k0 + aS * 16;
            float4 f0 = *(const float4*)p;
            float4 f1 = *(const float4*)(p + 4);
            float4 f2 = *(const float4*)(p + 8);
            float4 f3 = *(const float4*)(p + 12);
            sb[0] = h2(f0.x, f0.y); sb[1] = h2(f0.z, f0.w);
            sb[2] = h2(f1.x, f1.y); sb[3] = h2(f1.z, f1.w);
            sb[4] = h2(f2.x, f2.y); sb[5] = h2(f2.z, f2.w);
            sb[6] = h2(f3.x, f3.y); sb[7] = h2(f3.z, f3.w);
        } else {
            int gn = n0 + bn0i;
            int ks = k0 + bS * 16;
            float v[16];
#pragma unroll
            for (int r = 0; r < 16; r++)
                v[r] = (gn < N) ? Bb[(long)(ks + r) * ldb + gn] : 0.f;
#pragma unroll
            for (int j = 0; j < 8; j++) sb[j] = h2(v[2 * j], v[2 * j + 1]);
        }
    };

    auto STORE = [&](unsigned* Ad, unsigned* Bd) {
        unsigned* ap = Ad + aM * SROW + aS * 8;
#pragma unroll
        for (int j = 0; j < 4; j++)
            *(uint2*)(ap + 2 * j) = make_uint2(sa[j], sa[j + 4]);
        if (btrans) {
            unsigned* bp = Bd + aM * SROW + aS * 8;
#pragma unroll
            for (int j = 0; j < 4; j++)
                *(uint2*)(bp + 2 * j) = make_uint2(sb[j], sb[j + 4]);
        } else {
            unsigned* bp = Bd + bn0i * SROW + bS * 8;
#pragma unroll
            for (int j = 0; j < 4; j++)
                *(uint2*)(bp + 2 * j) = make_uint2(sb[j], sb[j + 4]);
        }
    };

    auto COMPUTE = [&](const unsigned* Ad, const unsigned* Bd) {
#pragma unroll
        for (int s = 0; s < 2; s++) {
            uint2 bf[4];
#pragma unroll
            for (int j = 0; j < 4; j++)
                bf[j] = *(const uint2*)&Bd[(wn * 32 + j * 8 + g) * SROW + s * 8 + 2 * t4];
#pragma unroll
            for (int i = 0; i < 4; i++) {
                int r = wm * 64 + i * 16 + g;
                uint2 lo = *(const uint2*)&Ad[r * SROW + s * 8 + 2 * t4];
                uint2 hi = *(const uint2*)&Ad[(r + 8) * SROW + s * 8 + 2 * t4];
#pragma unroll
                for (int j = 0; j < 4; j++)
                    MMA_F16(acc[i][j], lo.x, hi.x, lo.y, hi.y, bf[j].x, bf[j].y);
            }
        }
    };

    const int T = K / BKH;
    LOAD(0);
    STORE(As[0], Bs[0]);
    if (T > 1) LOAD(BKH);
    __syncthreads();
    for (int t = 0; t < T; t++) {
        int cur = t & 1;
        if (t + 1 < T) STORE(As[cur ^ 1], Bs[cur ^ 1]);
        if (t + 2 < T) LOAD((t + 2) * BKH);
        COMPUTE(As[cur], Bs[cur]);
        __syncthreads();
    }

#pragma unroll
    for (int i = 0; i < 4; i++) {
        int mr = m0 + wm * 64 + i * 16 + g;
#pragma unroll
        for (int j = 0; j < 4; j++) {
            int col = n0 + wn * 32 + j * 8 + (t4 << 1);
            if (col >= N) continue;
            float v00 = acc[i][j][0] * alpha;
            float v01 = acc[i][j][1] * alpha;
            float v10 = acc[i][j][2] * alpha;
            float v11 = acc[i][j][3] * alpha;
            if (hout) {
                *(__half2*)(Cbh + (long)mr * ldc + col) = __floats2half2_rn(v00, v01);
                *(__half2*)(Cbh + (long)(mr + 8) * ldc + col) = __floats2half2_rn(v10, v11);
            } else {
                *(float2*)(Cb + (long)mr * ldc + col) = make_float2(v00, v01);
                *(float2*)(Cb + (long)(mr + 8) * ldc + col) = make_float2(v10, v11);
            }
        }
    }
}

// ======================= launch =======================
extern "C" void kernel_launch(void* const* d_in, const int* in_sizes, int n_in,
                              void* d_out, int out_size) {
    const float* x      = (const float*)d_in[0];
    const float* mvn    = (const float*)d_in[1];
    const float* mvc    = (const float*)d_in[2];
    const float* qkv_w  = (const float*)d_in[3];
    const float* qkv_b  = (const float*)d_in[4];
    const float* proj_w = (const float*)d_in[5];
    const float* proj_b = (const float*)d_in[6];
    const float* mv_w1  = (const float*)d_in[7];
    const float* mv_b1  = (const float*)d_in[8];
    const float* mv_w2  = (const float*)d_in[9];
    const float* mv_b2  = (const float*)d_in[10];
    const float* mlp_w1 = (const float*)d_in[11];
    const float* mlp_b1 = (const float*)d_in[12];
    const float* mlp_w2 = (const float*)d_in[13];
    const float* mlp_b2 = (const float*)d_in[14];
    float* out = (float*)d_out;

    float *qkv, *scores, *x1, *x2;
    __half *qkvwT, *projwT, *mv1T, *mv2T, *mlp1T, *mlp2T;
    __half *mvnh, *mvch, *lnxh, *lnbh, *h1h, *attnh;
    cudaGetSymbolAddress((void**)&qkv,    g_qkv);
    cudaGetSymbolAddress((void**)&scores, g_scores);
    cudaGetSymbolAddress((void**)&x1,     g_x1);
    cudaGetSymbolAddress((void**)&x2,     g_x2);
    cudaGetSymbolAddress((void**)&qkvwT,  g_qkvwT);
    cudaGetSymbolAddress((void**)&projwT, g_projwT);
    cudaGetSymbolAddress((void**)&mv1T,   g_mv1T);
    cudaGetSymbolAddress((void**)&mv2T,   g_mv2T);
    cudaGetSymbolAddress((void**)&mlp1T,  g_mlp1T);
    cudaGetSymbolAddress((void**)&mlp2T,  g_mlp2T);
    cudaGetSymbolAddress((void**)&mvnh,   g_mvnh);
    cudaGetSymbolAddress((void**)&mvch,   g_mvch);
    cudaGetSymbolAddress((void**)&lnxh,   g_lnxh);
    cudaGetSymbolAddress((void**)&lnbh,   g_lnbh);
    cudaGetSymbolAddress((void**)&h1h,    g_h1h);
    cudaGetSymbolAddress((void**)&attnh,  g_attnh);

    cudaFuncSetAttribute(gemm_a, cudaFuncAttributeMaxDynamicSharedMemorySize, SMEMA);

    // 0) pre-convert weights (transposed) and mv tensors to fp16
    wt_kernel<<<dim3(3 * CDIM / 32, CDIM / 32), 256>>>(qkv_w, qkvwT, CDIM, 3 * CDIM);
    wt_kernel<<<dim3(CDIM / 32, CDIM / 32), 256>>>(proj_w, projwT, CDIM, CDIM);
    wt_kernel<<<dim3(HID / 32, KCAT / 32), 256>>>(mv_w1, mv1T, KCAT, HID);
    wt_kernel<<<dim3(CDIM / 32, HID / 32), 256>>>(mv_w2, mv2T, HID, CDIM);
    wt_kernel<<<dim3(HID / 32, CDIM / 32), 256>>>(mlp_w1, mlp1T, CDIM, HID);
    wt_kernel<<<dim3(CDIM / 32, HID / 32), 256>>>(mlp_w2, mlp2T, HID, CDIM);
    long n4 = (long)NTOK * MVD4 / 4;
    cvt_kernel<<<8192, 256>>>((const float4*)mvn, (__half2*)mvnh, n4);
    cvt_kernel<<<8192, 256>>>((const float4*)mvc, (__half2*)mvch, n4);

    // 1) lnx_h[j] = LN(x[(j+SHIFT)%N])   (fp16 out)
    ln_kernel<<<NTOK, 256>>>(x, lnxh, SHIFTK);

    // 2) qkv = lnxh @ qkvwT^T + qkv_b  (fp32 out)
    gemm_a<<<dim3(3 * CDIM / 128, NTOK / 128), 256, SMEMA>>>(
        lnxh, nullptr, nullptr, CDIM, CDIM, CDIM, 0, 0,
        qkvwT, CDIM, qkv, nullptr, 3 * CDIM, qkv_b, nullptr,
        CDIM, 0, 0, 8);

    // 3) scores = Q K^T / 8
    gemm_h<<<dim3(WS / BN, WS / BM, NZ), 256>>>(
        qkv, 3 * CDIM, qkv + CDIM, 3 * CDIM, 1, scores, WS,
        WS, HDIM, 0.125f, 0, 4,
        (long)WS * 3 * CDIM, HDIM,
        (long)WS * 3 * CDIM, HDIM,
        (long)WS * WS * HEADS, (long)WS * WS);

    // 4) softmax
    softmax_kernel<<<NZ * WS, 256>>>(scores);

    // 5) attn_h = P @ V (fp16 out)
    gemm_h<<<dim3(1, WS / BM, NZ), 256>>>(
        scores, WS, qkv + 2 * CDIM, 3 * CDIM, 0, (float*)attnh, CDIM,
        HDIM, WS, 1.f, 1, 1,
        (long)WS * WS * HEADS, (long)WS * WS,
        (long)WS * 3 * CDIM, HDIM,
        (long)WS * CDIM, HDIM);

    // 6) x1[(m+SHIFT)%N] = x[...] + attnh@projwT^T + proj_b
    gemm_a<<<dim3(CDIM / 128, NTOK / 128), 256, SMEMA>>>(
        attnh, nullptr, nullptr, CDIM, CDIM, CDIM, 0, 0,
        projwT, CDIM, x1, nullptr, CDIM, proj_b, x,
        CDIM, 2, SHIFTK, 8);

    // 7) mv branch
    ln_kernel<<<NTOK, 256>>>(x1, lnbh, 0);
    gemm_a<<<dim3(HID / 128, NTOK / 128), 256, SMEMA>>>(
        lnbh, mvnh, mvch, CDIM, CDIM + MVD4, CDIM, MVD4, MVD4,
        mv1T, KCAT, nullptr, h1h, HID, mv_b1, nullptr,
        KCAT, 1, 0, 8);
    gemm_a<<<dim3(CDIM / 128, NTOK / 128), 256, SMEMA>>>(
        h1h, nullptr, nullptr, HID, HID, HID, 0, 0,
        mv2T, HID, x2, nullptr, CDIM, mv_b2, x1,
        HID, 2, 0, 8);

    // 8) mlp branch
    ln_kernel<<<NTOK, 256>>>(x2, lnbh, 0);
    gemm_a<<<dim3(HID / 128, NTOK / 128), 256, SMEMA>>>(
        lnbh, nullptr, nullptr, CDIM, CDIM, CDIM, 0, 0,
        mlp1T, CDIM, nullptr, h1h, HID, mlp_b1, nullptr,
        CDIM, 1, 0, 8);
    gemm_a<<<dim3(CDIM / 128, NTOK / 128), 256, SMEMA>>>(
        h1h, nullptr, nullptr, HID, HID, HID, 0, 0,
        mlp2T, HID, out, nullptr, CDIM, mlp_b2, x2,
        HID, 2, 0, 8);
}

// round 14
// speedup vs baseline: 2.2969x; 1.0917x over previous
#include <cuda_runtime.h>
#include <cuda_fp16.h>
#include <cstdint>

// ---------------------------------------------------------------------------
// Round 14: R13 + fused flash attention (QK -> online softmax -> PV in one
// kernel; scores buffer & softmax kernel deleted) + qkv stored fp16.
// ---------------------------------------------------------------------------

#define NTOK 16384
#define CDIM 1024
#define HEADS 16
#define HDIM 64
#define WS 512
#define SHIFTK 256
#define MVD4 4096
#define KCAT 9216
#define HID 4096
#define NZ 512

// fp32 buffers
__device__ float g_x1    [(long)NTOK * CDIM];
__device__ float g_x2    [(long)NTOK * CDIM];
// fp16 buffers
__device__ __half g_qkvh [(long)NTOK * 3 * CDIM];
__device__ __half g_qkvwT[(long)3 * CDIM * CDIM];
__device__ __half g_projwT[(long)CDIM * CDIM];
__device__ __half g_mv1T [(long)HID * KCAT];
__device__ __half g_mv2T [(long)CDIM * HID];
__device__ __half g_mlp1T[(long)HID * CDIM];
__device__ __half g_mlp2T[(long)CDIM * HID];
__device__ __half g_mvnh [(long)NTOK * MVD4];
__device__ __half g_mvch [(long)NTOK * MVD4];
__device__ __half g_lnxh [(long)NTOK * CDIM];
__device__ __half g_lnbh [(long)NTOK * CDIM];
__device__ __half g_h1h  [(long)NTOK * HID];
__device__ __half g_attnh[(long)NTOK * CDIM];

// ======================= helpers =======================
__device__ __forceinline__ uint32_t smem_u32(const void* p) {
    uint32_t a;
    asm("{ .reg .u64 t; cvta.to.shared.u64 t, %1; cvt.u32.u64 %0, t; }"
        : "=r"(a) : "l"(p));
    return a;
}
__device__ __forceinline__ float gelu_tanh(float v) {
    return 0.5f * v * (1.f + tanhf(0.7978845608028654f * (v + 0.044715f * v * v * v)));
}
__device__ __forceinline__ unsigned h2(float a, float b) {
    __half2 h = __floats2half2_rn(a, b);
    return *(unsigned*)&h;
}
#define MMA_F16(c, a0, a1, a2, a3, b0, b1)                                    \
    asm volatile("mma.sync.aligned.m16n8k16.row.col.f32.f16.f16.f32 "         \
                 "{%0,%1,%2,%3},{%4,%5,%6,%7},{%8,%9},{%0,%1,%2,%3};"         \
                 : "+f"((c)[0]), "+f"((c)[1]), "+f"((c)[2]), "+f"((c)[3])     \
                 : "r"(a0), "r"(a1), "r"(a2), "r"(a3), "r"(b0), "r"(b1))
#define LDSM4(r0, r1, r2, r3, a)                                              \
    asm volatile("ldmatrix.sync.aligned.m8n8.x4.shared.b16 {%0,%1,%2,%3}, [%4];" \
                 : "=r"(r0), "=r"(r1), "=r"(r2), "=r"(r3) : "r"(a))
#define LDSM4T(r0, r1, r2, r3, a)                                             \
    asm volatile("ldmatrix.sync.aligned.m8n8.x4.trans.shared.b16 {%0,%1,%2,%3}, [%4];" \
                 : "=r"(r0), "=r"(r1), "=r"(r2), "=r"(r3) : "r"(a))
#define CPA(dst, src)                                                         \
    asm volatile("cp.async.cg.shared.global [%0], [%1], 16;"                  \
                 :: "r"(dst), "l"(src))

// ======================= conversion kernels =======================
__global__ __launch_bounds__(256) void wt_kernel(const float* __restrict__ W,
                                                 __half* __restrict__ WT,
                                                 int K, int N) {
    __shared__ float tile[32][33];
    int n0 = blockIdx.x * 32, k0 = blockIdx.y * 32;
    int tx = threadIdx.x & 31, ty = threadIdx.x >> 5;
#pragma unroll
    for (int r = 0; r < 4; r++)
        tile[ty + 8 * r][tx] = W[(long)(k0 + ty + 8 * r) * N + n0 + tx];
    __syncthreads();
#pragma unroll
    for (int r = 0; r < 4; r++)
        WT[(long)(n0 + ty + 8 * r) * K + k0 + tx] =
            __float2half_rn(tile[tx][ty + 8 * r]);
}

__global__ __launch_bounds__(256) void cvt_kernel(const float4* __restrict__ s,
                                                  __half2* __restrict__ d,
                                                  long n4) {
    long i = (long)blockIdx.x * blockDim.x + threadIdx.x;
    long stride = (long)gridDim.x * blockDim.x;
    for (; i < n4; i += stride) {
        float4 v = s[i];
        d[2 * i]     = __floats2half2_rn(v.x, v.y);
        d[2 * i + 1] = __floats2half2_rn(v.z, v.w);
    }
}

// ======================= LN (fp16 out) =======================
__global__ __launch_bounds__(256) void ln_kernel(const float* __restrict__ in,
                                                 __half* __restrict__ out,
                                                 int shift) {
    int row = blockIdx.x;
    int src = (row + shift) & (NTOK - 1);
    const float* p = in + (long)src * CDIM;
    int t = threadIdx.x;
    float v[4], s = 0.f, s2 = 0.f;
#pragma unroll
    for (int i = 0; i < 4; i++) {
        v[i] = p[t + i * 256];
        s += v[i]; s2 += v[i] * v[i];
    }
#pragma unroll
    for (int o = 16; o; o >>= 1) {
        s  += __shfl_xor_sync(~0u, s, o);
        s2 += __shfl_xor_sync(~0u, s2, o);
    }
    __shared__ float red0[8], red1[8];
    int wid = t >> 5, lid = t & 31;
    if (lid == 0) { red0[wid] = s; red1[wid] = s2; }
    __syncthreads();
    if (t < 32) {
        float a = (t < 8) ? red0[t] : 0.f;
        float b = (t < 8) ? red1[t] : 0.f;
#pragma unroll
        for (int o = 4; o; o >>= 1) {
            a += __shfl_xor_sync(~0u, a, o);
            b += __shfl_xor_sync(~0u, b, o);
        }
        if (t == 0) { red0[0] = a; red1[0] = b; }
    }
    __syncthreads();
    float mean = red0[0] * (1.f / CDIM);
    float var  = red1[0] * (1.f / CDIM) - mean * mean;
    float r = rsqrtf(var + 1e-6f);
    __half* q = out + (long)row * CDIM;
#pragma unroll
    for (int i = 0; i < 4; i++)
        q[t + i * 256] = __float2half_rn((v[i] - mean) * r);
}

// ======================= gemm_a (R13, + epi 3 = fp16 bias-out) ==========
#define SROWH 40
#define ABYTES (128 * SROWH * 2)
#define STAGEB (2 * ABYTES)
#define SMEMA (3 * STAGEB)

__global__ __launch_bounds__(256, 2) void gemm_a(
    const __half* __restrict__ A0, const __half* __restrict__ A1,
    const __half* __restrict__ A2, int kb1, int kb2,
    int lda0, int lda1, int lda2,
    const __half* __restrict__ Bt, int ldb,
    float* __restrict__ C, __half* __restrict__ Ch, int ldc,
    const float* __restrict__ bias, const float* __restrict__ resid,
    int K, int epi, int rowShift, int bandw)
{
    extern __shared__ __half dsm[];
    const uint32_t sb0 = smem_u32(dsm);

    int gx = gridDim.x, gy = gridDim.y;
    int id = blockIdx.y * gx + blockIdx.x;
    int per = bandw * gy;
    int band = id / per, rem = id - band * per;
    int bx = band * bandw + (rem % bandw);
    int by = rem / bandw;
    const int m0 = by * 128, n0 = bx * 128;

    const int tid = threadIdx.x, lane = tid & 31, wid = tid >> 5;
    const int wm = wid >> 2, wn = wid & 3;
    const int g = lane >> 2, t4 = lane & 3;

    float acc[4][4][4];
#pragma unroll
    for (int i = 0; i < 4; i++)
#pragma unroll
        for (int j = 0; j < 4; j++)
#pragma unroll
            for (int r = 0; r < 4; r++) acc[i][j][r] = 0.f;

    const int cRow = tid >> 1;
    const int cSeg = tid & 1;
    const uint32_t cOff = (uint32_t)(cRow * SROWH + cSeg * 16) * 2;
    const __half* bSrc = Bt + (long)(n0 + cRow) * ldb + cSeg * 16;

    auto ISSUE = [&](int stage, int k0) {
        uint32_t base = sb0 + stage * STAGEB;
        int gk = k0 + cSeg * 16;
        const __half* ap;
        if (gk < kb1)      ap = A0 + (long)(m0 + cRow) * lda0 + gk;
        else if (gk < kb2) ap = A1 + (long)(m0 + cRow) * lda1 + (gk - kb1);
        else               ap = A2 + (long)(m0 + cRow) * lda2 + (gk - kb2);
        uint32_t ad = base + cOff;
        CPA(ad, ap); CPA(ad + 16, ap + 8);
        uint32_t bd = base + ABYTES + cOff;
        const __half* bp = bSrc + k0;
        CPA(bd, bp); CPA(bd + 16, bp + 8);
        asm volatile("cp.async.commit_group;");
    };

    const int aRowB = (wm * 64 + (lane & 15)) * (SROWH * 2) + (lane >> 4) * 16;
    const int bRowB = (wn * 32 + ((lane >> 4) & 1) * 8 + (lane & 7)) * (SROWH * 2)
                      + ((lane >> 3) & 1) * 16;

    auto COMPUTE = [&](int stage) {
        uint32_t aB = sb0 + stage * STAGEB + aRowB;
        uint32_t bB = sb0 + stage * STAGEB + ABYTES + bRowB;
#pragma unroll
        for (int s = 0; s < 2; s++) {
            uint32_t bw[8];
            LDSM4(bw[0], bw[1], bw[2], bw[3], bB + s * 32);
            LDSM4(bw[4], bw[5], bw[6], bw[7], bB + 16 * (SROWH * 2) + s * 32);
#pragma unroll
            for (int i = 0; i < 4; i++) {
                uint32_t aw[4];
                LDSM4(aw[0], aw[1], aw[2], aw[3],
                      aB + i * 16 * (SROWH * 2) + s * 32);
#pragma unroll
                for (int j = 0; j < 4; j++)
                    MMA_F16(acc[i][j], aw[0], aw[1], aw[2], aw[3],
                            bw[2 * j], bw[2 * j + 1]);
            }
        }
    };

    const int T = K / 32;
    ISSUE(0, 0);
    ISSUE(1, 32);
    for (int t = 0; t < T; t++) {
        if (t + 2 <= T) asm volatile("cp.async.wait_group 1;" ::: "memory");
        else            asm volatile("cp.async.wait_group 0;" ::: "memory");
        __syncthreads();
        if (t + 2 < T) ISSUE((t + 2) % 3, (t + 2) * 32);
        COMPUTE(t % 3);
    }

#pragma unroll
    for (int i = 0; i < 4; i++) {
        int mr = m0 + wm * 64 + i * 16 + g;
        int r0 = rowShift ? ((mr + rowShift) & (NTOK - 1)) : mr;
        int r1 = rowShift ? ((mr + 8 + rowShift) & (NTOK - 1)) : (mr + 8);
#pragma unroll
        for (int j = 0; j < 4; j++) {
            int col = n0 + wn * 32 + j * 8 + (t4 << 1);
            float b0 = bias[col], b1 = bias[col + 1];
            float v00 = acc[i][j][0] + b0;
            float v01 = acc[i][j][1] + b1;
            float v10 = acc[i][j][2] + b0;
            float v11 = acc[i][j][3] + b1;
            if (epi == 1) {
                *(__half2*)(Ch + (long)r0 * ldc + col) =
                    __floats2half2_rn(gelu_tanh(v00), gelu_tanh(v01));
                *(__half2*)(Ch + (long)r1 * ldc + col) =
                    __floats2half2_rn(gelu_tanh(v10), gelu_tanh(v11));
            } else if (epi == 3) {
                *(__half2*)(Ch + (long)r0 * ldc + col) = __floats2half2_rn(v00, v01);
                *(__half2*)(Ch + (long)r1 * ldc + col) = __floats2half2_rn(v10, v11);
            } else {
                if (epi == 2) {
                    const float* q0 = resid + (long)r0 * ldc + col;
                    const float* q1 = resid + (long)r1 * ldc + col;
                    v00 += q0[0]; v01 += q0[1];
                    v10 += q1[0]; v11 += q1[1];
                }
                *(float2*)(C + (long)r0 * ldc + col) = make_float2(v00, v01);
                *(float2*)(C + (long)r1 * ldc + col) = make_float2(v10, v11);
            }
        }
    }
}

// ======================= fused flash attention ==========================
// grid (4 m-tiles, 512 z=w*16+h), 256 threads = 8 warps x 16 rows.
// Per warp: S = 16x128 fp32, online softmax (intra-warp stats), O = 16x64.
// Q/K frags via gemm_a's LDSM4 patterns; V via ldmatrix.x4.trans.
#define AROWB 144                      // 72 halves per row
#define QTILE (128 * AROWB)            // 18432 B
#define KVSTG (2 * QTILE)              // K+V per stage
#define SMEMF (QTILE + 3 * KVSTG)      // 129024 B

__global__ __launch_bounds__(256) void attn_fused(
    const __half* __restrict__ qkvh, __half* __restrict__ attnh)
{
    extern __shared__ char fsm[];
    const uint32_t sb = smem_u32(fsm);

    const int tid = threadIdx.x, lane = tid & 31, wid = tid >> 5;
    const int g = lane >> 2, t4 = lane & 3;
    const int z = blockIdx.y, w = z >> 4, hh = z & 15;
    const int m0 = blockIdx.x * 128;

    const __half* Qg = qkvh + ((long)(w * WS + m0)) * (3 * CDIM) + hh * HDIM;
    const __half* Kg = qkvh + ((long)(w * WS)) * (3 * CDIM) + CDIM + hh * HDIM;
    const __half* Vg = Kg + CDIM;

    // loaders: 2 threads per row, 64B each
    const int cRow = tid >> 1, cSeg = tid & 1;
    const uint32_t cOff = (uint32_t)(cRow * AROWB + cSeg * 64);

    auto ISSUE_Q = [&]() {
        uint32_t d = sb + cOff;
        const __half* s = Qg + (long)cRow * (3 * CDIM) + cSeg * 32;
        CPA(d, s); CPA(d + 16, s + 8); CPA(d + 32, s + 16); CPA(d + 48, s + 24);
    };
    auto ISSUE_KV = [&](int stage, int t) {
        uint32_t kb = sb + QTILE + stage * KVSTG + cOff;
        long tok = (long)(t * 128 + cRow) * (3 * CDIM);
        const __half* ks = Kg + tok + cSeg * 32;
        const __half* vs = Vg + tok + cSeg * 32;
        CPA(kb, ks); CPA(kb + 16, ks + 8); CPA(kb + 32, ks + 16); CPA(kb + 48, ks + 24);
        uint32_t vb = kb + QTILE;
        CPA(vb, vs); CPA(vb + 16, vs + 8); CPA(vb + 32, vs + 16); CPA(vb + 48, vs + 24);
        asm volatile("cp.async.commit_group;");
    };

    // fragment offsets
    const uint32_t qB = sb + (wid * 16 + (lane & 15)) * AROWB + (lane >> 4) * 16;
    const uint32_t kOffB = (((lane >> 4) & 1) * 8 + (lane & 7)) * AROWB
                           + ((lane >> 3) & 1) * 16;
    const uint32_t vOffB = (lane & 15) * AROWB + (lane >> 4) * 16;

    uint32_t qa[4][4];
    float od[8][4];
#pragma unroll
    for (int j = 0; j < 8; j++)
#pragma unroll
        for (int r = 0; r < 4; r++) od[j][r] = 0.f;
    float rmA = -1e30f, rmB = -1e30f, rsA = 0.f, rsB = 0.f;

    ISSUE_Q();
    ISSUE_KV(0, 0);          // group 0 (Q + KV0)
    ISSUE_KV(1, 1);          // group 1

    for (int t = 0; t < 4; t++) {
        if (t + 2 <= 4) asm volatile("cp.async.wait_group 1;" ::: "memory");
        else            asm volatile("cp.async.wait_group 0;" ::: "memory");
        __syncthreads();
        if (t == 0) {
#pragma unroll
            for (int s = 0; s < 4; s++)
                LDSM4(qa[s][0], qa[s][1], qa[s][2], qa[s][3], qB + s * 32);
        }
        if (t + 2 < 4) ISSUE_KV((t + 2) % 3, t + 2);

        const uint32_t Kb = sb + QTILE + (t % 3) * KVSTG;
        const uint32_t Vb = Kb + QTILE;

        // ---- QK: S[16 x 128] ----
        float sv[16][4];
#pragma unroll
        for (int j = 0; j < 16; j++)
#pragma unroll
            for (int r = 0; r < 4; r++) sv[j][r] = 0.f;
#pragma unroll
        for (int s = 0; s < 4; s++) {
#pragma unroll
            for (int p = 0; p < 8; p++) {
                uint32_t kb[4];
                LDSM4(kb[0], kb[1], kb[2], kb[3],
                      Kb + kOffB + p * (16 * AROWB) + s * 32);
                MMA_F16(sv[2 * p],     qa[s][0], qa[s][1], qa[s][2], qa[s][3],
                        kb[0], kb[1]);
                MMA_F16(sv[2 * p + 1], qa[s][0], qa[s][1], qa[s][2], qa[s][3],
                        kb[2], kb[3]);
            }
        }

        // ---- online softmax (rows g and g+8 of this warp's 16) ----
        float mA = -1e30f, mB = -1e30f;
#pragma unroll
        for (int j = 0; j < 16; j++) {
            sv[j][0] *= 0.125f; sv[j][1] *= 0.125f;
            sv[j][2] *= 0.125f; sv[j][3] *= 0.125f;
            mA = fmaxf(mA, fmaxf(sv[j][0], sv[j][1]));
            mB = fmaxf(mB, fmaxf(sv[j][2], sv[j][3]));
        }
        mA = fmaxf(mA, __shfl_xor_sync(~0u, mA, 1));
        mA = fmaxf(mA, __shfl_xor_sync(~0u, mA, 2));
        mB = fmaxf(mB, __shfl_xor_sync(~0u, mB, 1));
        mB = fmaxf(mB, __shfl_xor_sync(~0u, mB, 2));
        float nmA = fmaxf(rmA, mA), nmB = fmaxf(rmB, mB);
        float scA = __expf(rmA - nmA), scB = __expf(rmB - nmB);
        float sA = 0.f, sB = 0.f;
#pragma unroll
        for (int j = 0; j < 16; j++) {
            sv[j][0] = __expf(sv[j][0] - nmA);
            sv[j][1] = __expf(sv[j][1] - nmA);
            sv[j][2] = __expf(sv[j][2] - nmB);
            sv[j][3] = __expf(sv[j][3] - nmB);
            sA += sv[j][0] + sv[j][1];
            sB += sv[j][2] + sv[j][3];
        }
        sA += __shfl_xor_sync(~0u, sA, 1);
        sA += __shfl_xor_sync(~0u, sA, 2);
        sB += __shfl_xor_sync(~0u, sB, 1);
        sB += __shfl_xor_sync(~0u, sB, 2);
        rsA = rsA * scA + sA;
        rsB = rsB * scB + sB;
        rmA = nmA; rmB = nmB;
#pragma unroll
        for (int j = 0; j < 8; j++) {
            od[j][0] *= scA; od[j][1] *= scA;
            od[j][2] *= scB; od[j][3] *= scB;
        }

        // ---- PV: O += P @ V ----
#pragma unroll
        for (int sp = 0; sp < 8; sp++) {
            unsigned a0 = h2(sv[2 * sp][0],     sv[2 * sp][1]);
            unsigned a1 = h2(sv[2 * sp][2],     sv[2 * sp][3]);
            unsigned a2 = h2(sv[2 * sp + 1][0], sv[2 * sp + 1][1]);
            unsigned a3 = h2(sv[2 * sp + 1][2], sv[2 * sp + 1][3]);
#pragma unroll
            for (int q = 0; q < 4; q++) {
                uint32_t vb[4];
                LDSM4T(vb[0], vb[1], vb[2], vb[3],
                       Vb + vOffB + sp * (16 * AROWB) + q * 32);
                MMA_F16(od[2 * q],     a0, a1, a2, a3, vb[0], vb[1]);
                MMA_F16(od[2 * q + 1], a0, a1, a2, a3, vb[2], vb[3]);
            }
        }
        __syncthreads();
    }

    // ---- epilogue ----
    float invA = __frcp_rn(rsA), invB = __frcp_rn(rsB);
    long rowA = ((long)(w * WS + m0 + wid * 16 + g)) * CDIM + hh * HDIM;
    long rowB = rowA + 8L * CDIM;
#pragma unroll
    for (int j = 0; j < 8; j++) {
        int col = j * 8 + (t4 << 1);
        *(__half2*)(attnh + rowA + col) =
            __floats2half2_rn(od[j][0] * invA, od[j][1] * invA);
        *(__half2*)(attnh + rowB + col) =
            __floats2half2_rn(od[j][2] * invB, od[j][3] * invB);
    }
}

// ======================= launch =======================
extern "C" void kernel_launch(void* const* d_in, const int* in_sizes, int n_in,
                              void* d_out, int out_size) {
    const float* x      = (const float*)d_in[0];
    const float* mvn    = (const float*)d_in[1];
    const float* mvc    = (const float*)d_in[2];
    const float* qkv_w  = (const float*)d_in[3];
    const float* qkv_b  = (const float*)d_in[4];
    const float* proj_w = (const float*)d_in[5];
    const float* proj_b = (const float*)d_in[6];
    const float* mv_w1  = (const float*)d_in[7];
    const float* mv_b1  = (const float*)d_in[8];
    const float* mv_w2  = (const float*)d_in[9];
    const float* mv_b2  = (const float*)d_in[10];
    const float* mlp_w1 = (const float*)d_in[11];
    const float* mlp_b1 = (const float*)d_in[12];
    const float* mlp_w2 = (const float*)d_in[13];
    const float* mlp_b2 = (const float*)d_in[14];
    float* out = (float*)d_out;

    float *x1, *x2;
    __half *qkvh, *qkvwT, *projwT, *mv1T, *mv2T, *mlp1T, *mlp2T;
    __half *mvnh, *mvch, *lnxh, *lnbh, *h1h, *attnh;
    cudaGetSymbolAddress((void**)&x1,     g_x1);
    cudaGetSymbolAddress((void**)&x2,     g_x2);
    cudaGetSymbolAddress((void**)&qkvh,   g_qkvh);
    cudaGetSymbolAddress((void**)&qkvwT,  g_qkvwT);
    cudaGetSymbolAddress((void**)&projwT, g_projwT);
    cudaGetSymbolAddress((void**)&mv1T,   g_mv1T);
    cudaGetSymbolAddress((void**)&mv2T,   g_mv2T);
    cudaGetSymbolAddress((void**)&mlp1T,  g_mlp1T);
    cudaGetSymbolAddress((void**)&mlp2T,  g_mlp2T);
    cudaGetSymbolAddress((void**)&mvnh,   g_mvnh);
    cudaGetSymbolAddress((void**)&mvch,   g_mvch);
    cudaGetSymbolAddress((void**)&lnxh,   g_lnxh);
    cudaGetSymbolAddress((void**)&lnbh,   g_lnbh);
    cudaGetSymbolAddress((void**)&h1h,    g_h1h);
    cudaGetSymbolAddress((void**)&attnh,  g_attnh);

    cudaFuncSetAttribute(gemm_a, cudaFuncAttributeMaxDynamicSharedMemorySize, SMEMA);
    cudaFuncSetAttribute(attn_fused, cudaFuncAttributeMaxDynamicSharedMemorySize, SMEMF);

    // 0) pre-convert weights (transposed) and mv tensors to fp16
    wt_kernel<<<dim3(3 * CDIM / 32, CDIM / 32), 256>>>(qkv_w, qkvwT, CDIM, 3 * CDIM);
    wt_kernel<<<dim3(CDIM / 32, CDIM / 32), 256>>>(proj_w, projwT, CDIM, CDIM);
    wt_kernel<<<dim3(HID / 32, KCAT / 32), 256>>>(mv_w1, mv1T, KCAT, HID);
    wt_kernel<<<dim3(CDIM / 32, HID / 32), 256>>>(mv_w2, mv2T, HID, CDIM);
    wt_kernel<<<dim3(HID / 32, CDIM / 32), 256>>>(mlp_w1, mlp1T, CDIM, HID);
    wt_kernel<<<dim3(CDIM / 32, HID / 32), 256>>>(mlp_w2, mlp2T, HID, CDIM);
    long n4 = (long)NTOK * MVD4 / 4;
    cvt_kernel<<<8192, 256>>>((const float4*)mvn, (__half2*)mvnh, n4);
    cvt_kernel<<<8192, 256>>>((const float4*)mvc, (__half2*)mvch, n4);

    // 1) lnx_h[j] = LN(x[(j+SHIFT)%N])
    ln_kernel<<<NTOK, 256>>>(x, lnxh, SHIFTK);

    // 2) qkv_h = lnxh @ qkvwT^T + qkv_b   (fp16 out, epi=3)
    gemm_a<<<dim3(3 * CDIM / 128, NTOK / 128), 256, SMEMA>>>(
        lnxh, nullptr, nullptr, CDIM, CDIM, CDIM, 0, 0,
        qkvwT, CDIM, nullptr, qkvh, 3 * CDIM, qkv_b, nullptr,
        CDIM, 3, 0, 8);

    // 3-5) fused attention: scores+softmax+PV, attnh fp16
    attn_fused<<<dim3(4, NZ), 256, SMEMF>>>(qkvh, attnh);

    // 6) x1[(m+SHIFT)%N] = x[...] + attnh@projwT^T + proj_b
    gemm_a<<<dim3(CDIM / 128, NTOK / 128), 256, SMEMA>>>(
        attnh, nullptr, nullptr, CDIM, CDIM, CDIM, 0, 0,
        projwT, CDIM, x1, nullptr, CDIM, proj_b, x,
        CDIM, 2, SHIFTK, 8);

    // 7) mv branch
    ln_kernel<<<NTOK, 256>>>(x1, lnbh, 0);
    gemm_a<<<dim3(HID / 128, NTOK / 128), 256, SMEMA>>>(
        lnbh, mvnh, mvch, CDIM, CDIM + MVD4, CDIM, MVD4, MVD4,
        mv1T, KCAT, nullptr, h1h, HID, mv_b1, nullptr,
        KCAT, 1, 0, 8);
    gemm_a<<<dim3(CDIM / 128, NTOK / 128), 256, SMEMA>>>(
        h1h, nullptr, nullptr, HID, HID, HID, 0, 0,
        mv2T, HID, x2, nullptr, CDIM, mv_b2, x1,
        HID, 2, 0, 8);

    // 8) mlp branch
    ln_kernel<<<NTOK, 256>>>(x2, lnbh, 0);
    gemm_a<<<dim3(HID / 128, NTOK / 128), 256, SMEMA>>>(
        lnbh, nullptr, nullptr, CDIM, CDIM, CDIM, 0, 0,
        mlp1T, CDIM, nullptr, h1h, HID, mlp_b1, nullptr,
        CDIM, 1, 0, 8);
    gemm_a<<<dim3(CDIM / 128, NTOK / 128), 256, SMEMA>>>(
        h1h, nullptr, nullptr, HID, HID, HID, 0, 0,
        mlp2T, HID, out, nullptr, CDIM, mlp_b2, x2,
        HID, 2, 0, 8);
}